// round 4
// baseline (speedup 1.0000x reference)
#include <cuda_runtime.h>
#include <cstdint>

#define BATCH 8192
#define NV    1000
#define CHEBK 5
#define NF    5
#define HIDD  256
#define NOUT  10
#define POOLD 625
#define MAXW  32
#define BT    4

// ---------------- scratch ----------------
__device__ int2  g_ell[NV * MAXW];     // packed {col, __float_as_int(val)}
__device__ int   g_ell_len[NV];
__device__ int   g_perm[NV];           // degree-sorted node order
__device__ float g_pool[(size_t)BATCH * POOLD];
__device__ float g_z1[(size_t)BATCH * HIDD];
__device__ float g_z2[(size_t)BATCH * HIDD];

// ---------------- kernel 1: build ELL of Lr = 2*L/lmax - I (warp/row) ----------------
__global__ void build_ell(const float* __restrict__ L, const float* __restrict__ lmax) {
    const int warp = (blockIdx.x * blockDim.x + threadIdx.x) >> 5;
    const int lane = threadIdx.x & 31;
    if (warp >= NV) return;
    const int v = warp;
    const float inv = 2.0f / lmax[0];
    int cnt = 0;
    #pragma unroll 4
    for (int c = 0; c < (NV + 31) / 32; ++c) {
        const int u = c * 32 + lane;
        float val = 0.0f;
        if (u < NV) val = L[(size_t)v * NV + u] * inv - (u == v ? 1.0f : 0.0f);
        const bool nz = (val != 0.0f);
        const unsigned m = __ballot_sync(0xffffffffu, nz);
        if (nz) {
            const int idx = cnt + __popc(m & ((1u << lane) - 1u));
            if (idx < MAXW) g_ell[v * MAXW + idx] = make_int2(u, __float_as_int(val));
        }
        cnt += __popc(m);
    }
    if (lane == 0) g_ell_len[v] = cnt < MAXW ? cnt : MAXW;
}

// ---------------- kernel 1b: counting sort of nodes by degree -> g_perm ----------------
// Order within a bin is nondeterministic (atomics) but the RESULT is invariant:
// perm only chooses which thread computes which node; per-node fp-op order is fixed.
__global__ void sort_nodes() {
    __shared__ int hist[MAXW + 1];
    __shared__ int off[MAXW + 1];
    const int tid = threadIdx.x;
    if (tid <= MAXW) hist[tid] = 0;
    __syncthreads();
    for (int v = tid; v < NV; v += blockDim.x) atomicAdd(&hist[g_ell_len[v]], 1);
    __syncthreads();
    if (tid == 0) {
        int run = 0;
        for (int b = 0; b <= MAXW; ++b) { off[b] = run; run += hist[b]; }
    }
    __syncthreads();
    for (int v = tid; v < NV; v += blockDim.x) {
        const int pos = atomicAdd(&off[g_ell_len[v]], 1);
        g_perm[pos] = v;
    }
}

// ---------------- kernel 2: fused cheby + cl1 + relu + maxpool ----------------
// BT=4 batch columns per CTA; 5 planes sT[k][v][4] = 80000 B -> 2 CTAs/SM.
// Thread p handles node v = g_perm[p] (degree-balanced warps). Planes indexed by
// true node id v so gathers (by col) and the pooling epilogue need no indirection.
__global__ __launch_bounds__(1024, 2)
void cheby_fused(const float* __restrict__ x,
                 const float* __restrict__ W,
                 const float* __restrict__ bias) {
    extern __shared__ float sT[];                 // [CHEBK][NV][BT] + 32 floats W/b
    float* sW = sT + CHEBK * NV * BT;             // [NF*CHEBK] then [NF]
    const int b0  = blockIdx.x * BT;
    const int tid = threadIdx.x;

    if (tid < NF * CHEBK) sW[tid] = W[tid];
    if (tid < NF) sW[NF * CHEBK + tid] = bias[tid];

    // T0[v][bb] = x[b0+bb][v]  (coalesced in v)
    #pragma unroll
    for (int i = tid; i < NV * BT; i += 1024) {
        const int bb = i / NV, v = i - bb * NV;
        sT[v * BT + bb] = x[(size_t)(b0 + bb) * NV + v];
    }
    __syncthreads();

    int v = 0, len = 0;
    const int2* __restrict__ ell = g_ell;
    if (tid < NV) {
        v = g_perm[tid];
        len = g_ell_len[v];
        ell = g_ell + v * MAXW;
    }

    #pragma unroll
    for (int k = 1; k < CHEBK; ++k) {
        const float* __restrict__ Tm1 = sT + (k - 1) * (NV * BT);
        float*       __restrict__ Tk  = sT + k * (NV * BT);
        if (tid < NV) {
            float ax = 0.0f, ay = 0.0f, az = 0.0f, aw = 0.0f;
            #pragma unroll 4
            for (int j = 0; j < len; ++j) {
                const int2 e = __ldg(&ell[j]);
                const float w = __int_as_float(e.y);
                const float4 t = *reinterpret_cast<const float4*>(Tm1 + e.x * BT);
                ax = fmaf(w, t.x, ax);
                ay = fmaf(w, t.y, ay);
                az = fmaf(w, t.z, az);
                aw = fmaf(w, t.w, aw);
            }
            float4* to = reinterpret_cast<float4*>(Tk + v * BT);
            if (k == 1) {
                *to = make_float4(ax, ay, az, aw);
            } else {
                const float4 m2 = *reinterpret_cast<const float4*>(sT + (k - 2) * (NV * BT) + v * BT);
                *to = make_float4(2.0f * ax - m2.x, 2.0f * ay - m2.y,
                                  2.0f * az - m2.z, 2.0f * aw - m2.w);
            }
        }
        __syncthreads();
    }

    // epilogue: 125 groups * 4 bb = 500 items
    if (tid < 125 * BT) {
        const int bb = tid & (BT - 1);
        const int g  = tid / BT;
        float m[NF];
        #pragma unroll
        for (int f = 0; f < NF; ++f) m[f] = -3.4e38f;
        #pragma unroll
        for (int vi = 0; vi < 8; ++vi) {
            const int vv = g * 8 + vi;
            float t[CHEBK];
            #pragma unroll
            for (int k = 0; k < CHEBK; ++k) t[k] = sT[k * (NV * BT) + vv * BT + bb];
            #pragma unroll
            for (int f = 0; f < NF; ++f) {
                float s = sW[NF * CHEBK + f];
                #pragma unroll
                for (int k = 0; k < CHEBK; ++k) s = fmaf(sW[f * CHEBK + k], t[k], s);
                m[f] = fmaxf(m[f], s);
            }
        }
        float* op = g_pool + (size_t)(b0 + bb) * POOLD + g * NF;
        #pragma unroll
        for (int f = 0; f < NF; ++f) op[f] = fmaxf(m[f], 0.0f);
    }
}

// ---------------- kernels 3/4: SGEMM C = A @ Bw^T + fused epilogue ----------------
// 128x64 tiles, 256 threads, 8x4 microtile -> 256 CTAs per launch.
#define BM 128
#define BN 64
#define BKg 16

template <int EPI>
__global__ __launch_bounds__(256, 3)
void gemm_nt(const float* __restrict__ A, const float* __restrict__ Bw,
             const float* __restrict__ bias,
             const float* __restrict__ bn_gamma, const float* __restrict__ bn_beta,
             const float* __restrict__ bn_mean,  const float* __restrict__ bn_var,
             float* __restrict__ C, int Kd, int N) {
    __shared__ float As[2][BKg][BM + 4];
    __shared__ float Bs[2][BKg][BN + 4];

    const int tid  = threadIdx.x;
    const int tx   = tid & 15;        // 0..15 -> col block of 4
    const int ty   = tid >> 4;        // 0..15 -> row block of 8
    const int row0 = blockIdx.y * BM;
    const int col0 = blockIdx.x * BN;

    float acc[8][4];
    #pragma unroll
    for (int i = 0; i < 8; ++i)
        #pragma unroll
        for (int j = 0; j < 4; ++j) acc[i][j] = 0.0f;

    const int ntiles = (Kd + BKg - 1) / BKg;

    float ra[8], rb[4];
    auto load_tile = [&](int kt) {
        #pragma unroll
        for (int i = 0; i < 8; ++i) {
            const int idx = tid + i * 256;
            const int mm = idx >> 4, kk = idx & 15;
            const int kg = kt + kk;
            ra[i] = (kg < Kd) ? A[(size_t)(row0 + mm) * Kd + kg] : 0.0f;
        }
        #pragma unroll
        for (int i = 0; i < 4; ++i) {
            const int idx = tid + i * 256;
            const int mm = idx >> 4, kk = idx & 15;
            const int kg = kt + kk;
            rb[i] = (kg < Kd) ? Bw[(size_t)(col0 + mm) * Kd + kg] : 0.0f;
        }
    };
    auto store_tile = [&](int p) {
        #pragma unroll
        for (int i = 0; i < 8; ++i) {
            const int idx = tid + i * 256;
            As[p][idx & 15][idx >> 4] = ra[i];
        }
        #pragma unroll
        for (int i = 0; i < 4; ++i) {
            const int idx = tid + i * 256;
            Bs[p][idx & 15][idx >> 4] = rb[i];
        }
    };

    load_tile(0);
    store_tile(0);
    __syncthreads();

    int p = 0;
    for (int t = 0; t < ntiles; ++t) {
        if (t + 1 < ntiles) load_tile((t + 1) * BKg);
        #pragma unroll
        for (int kk = 0; kk < BKg; ++kk) {
            const float4* ap = reinterpret_cast<const float4*>(&As[p][kk][ty * 8]);
            const float4  a0 = ap[0], a1 = ap[1];
            const float4  b0 = *reinterpret_cast<const float4*>(&Bs[p][kk][tx * 4]);
            const float a[8] = {a0.x, a0.y, a0.z, a0.w, a1.x, a1.y, a1.z, a1.w};
            const float b[4] = {b0.x, b0.y, b0.z, b0.w};
            #pragma unroll
            for (int i = 0; i < 8; ++i)
                #pragma unroll
                for (int j = 0; j < 4; ++j) acc[i][j] = fmaf(a[i], b[j], acc[i][j]);
        }
        if (t + 1 < ntiles) {
            __syncthreads();
            store_tile(p ^ 1);
            __syncthreads();
        }
        p ^= 1;
    }

    // per-column epilogue coefficients
    float cb[4], cs[4][4], ct[4][4];
    #pragma unroll
    for (int j = 0; j < 4; ++j) {
        const int col = col0 + tx * 4 + j;
        cb[j] = __ldg(bias + col);
        if (EPI == 0) {
            #pragma unroll
            for (int l = 0; l < 4; ++l) {
                const int idx = l * HIDD + col;
                const float s = __ldg(bn_gamma + idx) * rsqrtf(__ldg(bn_var + idx) + 1e-5f);
                cs[j][l] = s;
                ct[j][l] = __ldg(bn_beta + idx) - __ldg(bn_mean + idx) * s;
            }
        }
    }

    #pragma unroll
    for (int i = 0; i < 8; ++i) {
        const int row = row0 + ty * 8 + i;
        float4 o;
        float* ov = &o.x;
        #pragma unroll
        for (int j = 0; j < 4; ++j) {
            float y = acc[i][j] + cb[j];
            if (EPI == 0) {
                float z = 0.0f;
                #pragma unroll
                for (int l = 0; l < 4; ++l) {
                    y = fmaxf(fmaf(y, cs[j][l], ct[j][l]), 0.0f);
                    z = fmaxf(z, y);
                }
                ov[j] = z;
            } else {
                ov[j] = fmaxf(y, 0.0f);
            }
        }
        *reinterpret_cast<float4*>(&C[(size_t)row * N + col0 + tx * 4]) = o;
    }
}

// ---------------- kernel 5: lin2 + log_softmax ----------------
__global__ void lin2_lsm(const float* __restrict__ Z2, const float* __restrict__ W2,
                         const float* __restrict__ b2, float* __restrict__ out) {
    const int gw   = (blockIdx.x * blockDim.x + threadIdx.x) >> 5;
    const int lane = threadIdx.x & 31;
    if (gw >= BATCH) return;
    const float* zr = Z2 + (size_t)gw * HIDD;
    float z[8];
    #pragma unroll
    for (int j = 0; j < 8; ++j) z[j] = zr[lane + 32 * j];

    float logit[NOUT];
    #pragma unroll
    for (int o = 0; o < NOUT; ++o) {
        float p = 0.0f;
        #pragma unroll
        for (int j = 0; j < 8; ++j) p += z[j] * __ldg(W2 + o * HIDD + lane + 32 * j);
        #pragma unroll
        for (int off = 16; off; off >>= 1) p += __shfl_xor_sync(0xffffffffu, p, off);
        logit[o] = p + __ldg(b2 + o);
    }
    float m = logit[0];
    #pragma unroll
    for (int o = 1; o < NOUT; ++o) m = fmaxf(m, logit[o]);
    float s = 0.0f;
    #pragma unroll
    for (int o = 0; o < NOUT; ++o) s += expf(logit[o] - m);
    const float lse = m + logf(s);
    if (lane < NOUT) out[(size_t)gw * NOUT + lane] = logit[lane] - lse;
}

// ---------------- launcher ----------------
extern "C" void kernel_launch(void* const* d_in, const int* in_sizes, int n_in,
                              void* d_out, int out_size) {
    const float* x        = (const float*)d_in[0];
    const float* L        = (const float*)d_in[1];
    const float* lmax     = (const float*)d_in[2];
    const float* cl1W     = (const float*)d_in[3];
    const float* cl1b     = (const float*)d_in[4];
    const float* fc1W     = (const float*)d_in[5];
    const float* fc1b     = (const float*)d_in[6];
    const float* bn_gamma = (const float*)d_in[7];
    const float* bn_beta  = (const float*)d_in[8];
    const float* bn_mean  = (const float*)d_in[9];
    const float* bn_var   = (const float*)d_in[10];
    const float* lin1W    = (const float*)d_in[11];
    const float* lin1b    = (const float*)d_in[12];
    const float* lin2W    = (const float*)d_in[13];
    const float* lin2b    = (const float*)d_in[14];
    float* out = (float*)d_out;

    float *pPool, *pZ1, *pZ2;
    cudaGetSymbolAddress((void**)&pPool, g_pool);
    cudaGetSymbolAddress((void**)&pZ1,  g_z1);
    cudaGetSymbolAddress((void**)&pZ2,  g_z2);

    // 1) sparse extraction of Lr + degree sort
    build_ell<<<(NV * 32 + 255) / 256, 256>>>(L, lmax);
    sort_nodes<<<1, 1024>>>();

    // 2) fused chebyshev + cl1 + relu + maxpool (2 CTAs/SM)
    const int smem = (CHEBK * NV * BT + 32) * (int)sizeof(float);  // 80128 B
    cudaFuncSetAttribute(cheby_fused, cudaFuncAttributeMaxDynamicSharedMemorySize, smem);
    cheby_fused<<<BATCH / BT, 1024, smem>>>(x, cl1W, cl1b);

    // 3) fc1 + BN x4 + relu + JK-max  (M=8192, N=256, K=625)
    dim3 grid(HIDD / BN, BATCH / BM);   // (4, 64) = 256 CTAs
    gemm_nt<0><<<grid, 256>>>(pPool, fc1W, fc1b, bn_gamma, bn_beta, bn_mean, bn_var,
                              pZ1, POOLD, HIDD);

    // 4) lin1 + relu  (M=8192, N=256, K=256)
    gemm_nt<1><<<grid, 256>>>(pZ1, lin1W, lin1b, nullptr, nullptr, nullptr, nullptr,
                              pZ2, HIDD, HIDD);

    // 5) lin2 + log_softmax
    lin2_lsm<<<BATCH / 8, 256>>>(pZ2, lin2W, lin2b, out);
}

// round 6
// speedup vs baseline: 1.0798x; 1.0798x over previous
#include <cuda_runtime.h>
#include <cstdint>

#define BATCH 8192
#define NV    1000
#define CHEBK 5
#define NF    5
#define HIDD  256
#define NOUT  10
#define POOLD 625
#define MAXW  32
#define BT    4

// ---------------- scratch ----------------
__device__ int2  g_ell[NV * MAXW];     // packed {col, __float_as_int(val)}
__device__ int   g_ell_len[NV];
__device__ int   g_perm[NV];           // degree-sorted node order
__device__ float g_pool[(size_t)BATCH * POOLD];
__device__ float g_z1[(size_t)BATCH * HIDD];
__device__ float g_z2[(size_t)BATCH * HIDD];

// ---------------- kernel 1: build ELL of Lr = 2*L/lmax - I (warp/row) ----------------
__global__ void build_ell(const float* __restrict__ L, const float* __restrict__ lmax) {
    const int warp = (blockIdx.x * blockDim.x + threadIdx.x) >> 5;
    const int lane = threadIdx.x & 31;
    if (warp >= NV) return;
    const int v = warp;
    const float inv = 2.0f / lmax[0];
    int cnt = 0;
    #pragma unroll 4
    for (int c = 0; c < (NV + 31) / 32; ++c) {
        const int u = c * 32 + lane;
        float val = 0.0f;
        if (u < NV) val = L[(size_t)v * NV + u] * inv - (u == v ? 1.0f : 0.0f);
        const bool nz = (val != 0.0f);
        const unsigned m = __ballot_sync(0xffffffffu, nz);
        if (nz) {
            const int idx = cnt + __popc(m & ((1u << lane) - 1u));
            if (idx < MAXW) g_ell[v * MAXW + idx] = make_int2(u, __float_as_int(val));
        }
        cnt += __popc(m);
    }
    if (lane == 0) g_ell_len[v] = cnt < MAXW ? cnt : MAXW;
}

// ---------------- kernel 1b: counting sort of nodes by degree -> g_perm ----------------
__global__ void sort_nodes() {
    __shared__ int hist[MAXW + 1];
    __shared__ int off[MAXW + 1];
    const int tid = threadIdx.x;
    if (tid <= MAXW) hist[tid] = 0;
    __syncthreads();
    for (int v = tid; v < NV; v += blockDim.x) atomicAdd(&hist[g_ell_len[v]], 1);
    __syncthreads();
    if (tid == 0) {
        int run = 0;
        for (int b = 0; b <= MAXW; ++b) { off[b] = run; run += hist[b]; }
    }
    __syncthreads();
    for (int v = tid; v < NV; v += blockDim.x) {
        const int pos = atomicAdd(&off[g_ell_len[v]], 1);
        g_perm[pos] = v;
    }
}

// ---------------- kernel 2: fused cheby + cl1 + relu + maxpool ----------------
// 512 threads, TWO sorted-adjacent nodes per thread (balanced + 2 indep chains),
// BT=4 batch columns; 5 planes = 80 KB -> 2 CTAs/SM with no register cap spills.
__global__ __launch_bounds__(512, 2)
void cheby_fused(const float* __restrict__ x,
                 const float* __restrict__ W,
                 const float* __restrict__ bias) {
    extern __shared__ float sT[];                 // [CHEBK][NV][BT] + 32 floats W/b
    float* sW = sT + CHEBK * NV * BT;
    const int b0  = blockIdx.x * BT;
    const int tid = threadIdx.x;

    if (tid < NF * CHEBK) sW[tid] = W[tid];
    if (tid < NF) sW[NF * CHEBK + tid] = bias[tid];

    // T0[v][bb] = x[b0+bb][v]  (coalesced in v)
    #pragma unroll
    for (int i = tid; i < NV * BT; i += 512) {
        const int bb = i / NV, v = i - bb * NV;
        sT[v * BT + bb] = x[(size_t)(b0 + bb) * NV + v];
    }
    __syncthreads();

    // two nodes per thread, adjacent in degree-sorted order
    int va = 0, vb = 0, la = 0, lb = 0;
    const int2 *ea = g_ell, *eb = g_ell;
    const int n0 = 2 * tid, n1 = 2 * tid + 1;
    if (n0 < NV) { va = g_perm[n0]; la = g_ell_len[va]; ea = g_ell + va * MAXW; }
    if (n1 < NV) { vb = g_perm[n1]; lb = g_ell_len[vb]; eb = g_ell + vb * MAXW; }
    const int lm = la > lb ? la : lb;

    #pragma unroll
    for (int k = 1; k < CHEBK; ++k) {
        const float* __restrict__ Tm1 = sT + (k - 1) * (NV * BT);
        float*       __restrict__ Tk  = sT + k * (NV * BT);
        if (n0 < NV) {
            float4 A = make_float4(0.f, 0.f, 0.f, 0.f);
            float4 Bv = make_float4(0.f, 0.f, 0.f, 0.f);
            #pragma unroll 2
            for (int j = 0; j < lm; ++j) {
                if (j < la) {
                    const int2 e = __ldg(&ea[j]);
                    const float w = __int_as_float(e.y);
                    const float4 t = *reinterpret_cast<const float4*>(Tm1 + e.x * BT);
                    A.x = fmaf(w, t.x, A.x); A.y = fmaf(w, t.y, A.y);
                    A.z = fmaf(w, t.z, A.z); A.w = fmaf(w, t.w, A.w);
                }
                if (j < lb) {
                    const int2 e = __ldg(&eb[j]);
                    const float w = __int_as_float(e.y);
                    const float4 t = *reinterpret_cast<const float4*>(Tm1 + e.x * BT);
                    Bv.x = fmaf(w, t.x, Bv.x); Bv.y = fmaf(w, t.y, Bv.y);
                    Bv.z = fmaf(w, t.z, Bv.z); Bv.w = fmaf(w, t.w, Bv.w);
                }
            }
            if (k == 1) {
                *reinterpret_cast<float4*>(Tk + va * BT) = A;
                if (n1 < NV) *reinterpret_cast<float4*>(Tk + vb * BT) = Bv;
            } else {
                const float* Tm2 = sT + (k - 2) * (NV * BT);
                const float4 ma = *reinterpret_cast<const float4*>(Tm2 + va * BT);
                *reinterpret_cast<float4*>(Tk + va * BT) =
                    make_float4(2.f * A.x - ma.x, 2.f * A.y - ma.y,
                                2.f * A.z - ma.z, 2.f * A.w - ma.w);
                if (n1 < NV) {
                    const float4 mb = *reinterpret_cast<const float4*>(Tm2 + vb * BT);
                    *reinterpret_cast<float4*>(Tk + vb * BT) =
                        make_float4(2.f * Bv.x - mb.x, 2.f * Bv.y - mb.y,
                                    2.f * Bv.z - mb.z, 2.f * Bv.w - mb.w);
                }
            }
        }
        __syncthreads();
    }

    // epilogue: 125 groups * 4 bb = 500 items
    if (tid < 125 * BT) {
        const int bb = tid & (BT - 1);
        const int g  = tid / BT;
        float m[NF];
        #pragma unroll
        for (int f = 0; f < NF; ++f) m[f] = -3.4e38f;
        #pragma unroll
        for (int vi = 0; vi < 8; ++vi) {
            const int vv = g * 8 + vi;
            float t[CHEBK];
            #pragma unroll
            for (int k = 0; k < CHEBK; ++k) t[k] = sT[k * (NV * BT) + vv * BT + bb];
            #pragma unroll
            for (int f = 0; f < NF; ++f) {
                float s = sW[NF * CHEBK + f];
                #pragma unroll
                for (int k = 0; k < CHEBK; ++k) s = fmaf(sW[f * CHEBK + k], t[k], s);
                m[f] = fmaxf(m[f], s);
            }
        }
        float* op = g_pool + (size_t)(b0 + bb) * POOLD + g * NF;
        #pragma unroll
        for (int f = 0; f < NF; ++f) op[f] = fmaxf(m[f], 0.0f);
    }
}

// ---------------- kernels 3/4: SGEMM C = A @ Bw^T + fused epilogue ----------------
#define BM 128
#define BN 64
#define BKg 16

template <int EPI>
__global__ __launch_bounds__(256, 3)
void gemm_nt(const float* __restrict__ A, const float* __restrict__ Bw,
             const float* __restrict__ bias,
             const float* __restrict__ bn_gamma, const float* __restrict__ bn_beta,
             const float* __restrict__ bn_mean,  const float* __restrict__ bn_var,
             float* __restrict__ C, int Kd, int N) {
    __shared__ float As[2][BKg][BM + 4];
    __shared__ float Bs[2][BKg][BN + 4];

    const int tid  = threadIdx.x;
    const int tx   = tid & 15;
    const int ty   = tid >> 4;
    const int row0 = blockIdx.y * BM;
    const int col0 = blockIdx.x * BN;

    float acc[8][4];
    #pragma unroll
    for (int i = 0; i < 8; ++i)
        #pragma unroll
        for (int j = 0; j < 4; ++j) acc[i][j] = 0.0f;

    const int ntiles = (Kd + BKg - 1) / BKg;

    float ra[8], rb[4];
    auto load_tile = [&](int kt) {
        #pragma unroll
        for (int i = 0; i < 8; ++i) {
            const int idx = tid + i * 256;
            const int mm = idx >> 4, kk = idx & 15;
            const int kg = kt + kk;
            ra[i] = (kg < Kd) ? A[(size_t)(row0 + mm) * Kd + kg] : 0.0f;
        }
        #pragma unroll
        for (int i = 0; i < 4; ++i) {
            const int idx = tid + i * 256;
            const int mm = idx >> 4, kk = idx & 15;
            const int kg = kt + kk;
            rb[i] = (kg < Kd) ? Bw[(size_t)(col0 + mm) * Kd + kg] : 0.0f;
        }
    };
    auto store_tile = [&](int p) {
        #pragma unroll
        for (int i = 0; i < 8; ++i) {
            const int idx = tid + i * 256;
            As[p][idx & 15][idx >> 4] = ra[i];
        }
        #pragma unroll
        for (int i = 0; i < 4; ++i) {
            const int idx = tid + i * 256;
            Bs[p][idx & 15][idx >> 4] = rb[i];
        }
    };

    load_tile(0);
    store_tile(0);
    __syncthreads();

    int p = 0;
    for (int t = 0; t < ntiles; ++t) {
        if (t + 1 < ntiles) load_tile((t + 1) * BKg);
        #pragma unroll
        for (int kk = 0; kk < BKg; ++kk) {
            const float4* ap = reinterpret_cast<const float4*>(&As[p][kk][ty * 8]);
            const float4  a0 = ap[0], a1 = ap[1];
            const float4  b0 = *reinterpret_cast<const float4*>(&Bs[p][kk][tx * 4]);
            const float a[8] = {a0.x, a0.y, a0.z, a0.w, a1.x, a1.y, a1.z, a1.w};
            const float b[4] = {b0.x, b0.y, b0.z, b0.w};
            #pragma unroll
            for (int i = 0; i < 8; ++i)
                #pragma unroll
                for (int j = 0; j < 4; ++j) acc[i][j] = fmaf(a[i], b[j], acc[i][j]);
        }
        if (t + 1 < ntiles) {
            __syncthreads();
            store_tile(p ^ 1);
            __syncthreads();
        }
        p ^= 1;
    }

    float cb[4], cs[4][4], ct[4][4];
    #pragma unroll
    for (int j = 0; j < 4; ++j) {
        const int col = col0 + tx * 4 + j;
        cb[j] = __ldg(bias + col);
        if (EPI == 0) {
            #pragma unroll
            for (int l = 0; l < 4; ++l) {
                const int idx = l * HIDD + col;
                const float s = __ldg(bn_gamma + idx) * rsqrtf(__ldg(bn_var + idx) + 1e-5f);
                cs[j][l] = s;
                ct[j][l] = __ldg(bn_beta + idx) - __ldg(bn_mean + idx) * s;
            }
        }
    }

    #pragma unroll
    for (int i = 0; i < 8; ++i) {
        const int row = row0 + ty * 8 + i;
        float4 o;
        float* ov = &o.x;
        #pragma unroll
        for (int j = 0; j < 4; ++j) {
            float y = acc[i][j] + cb[j];
            if (EPI == 0) {
                float z = 0.0f;
                #pragma unroll
                for (int l = 0; l < 4; ++l) {
                    y = fmaxf(fmaf(y, cs[j][l], ct[j][l]), 0.0f);
                    z = fmaxf(z, y);
                }
                ov[j] = z;
            } else {
                ov[j] = fmaxf(y, 0.0f);
            }
        }
        *reinterpret_cast<float4*>(&C[(size_t)row * N + col0 + tx * 4]) = o;
    }
}

// ---------------- kernel 5: lin2 + log_softmax ----------------
__global__ void lin2_lsm(const float* __restrict__ Z2, const float* __restrict__ W2,
                         const float* __restrict__ b2, float* __restrict__ out) {
    const int gw   = (blockIdx.x * blockDim.x + threadIdx.x) >> 5;
    const int lane = threadIdx.x & 31;
    if (gw >= BATCH) return;
    const float* zr = Z2 + (size_t)gw * HIDD;
    float z[8];
    #pragma unroll
    for (int j = 0; j < 8; ++j) z[j] = zr[lane + 32 * j];

    float logit[NOUT];
    #pragma unroll
    for (int o = 0; o < NOUT; ++o) {
        float p = 0.0f;
        #pragma unroll
        for (int j = 0; j < 8; ++j) p += z[j] * __ldg(W2 + o * HIDD + lane + 32 * j);
        #pragma unroll
        for (int off = 16; off; off >>= 1) p += __shfl_xor_sync(0xffffffffu, p, off);
        logit[o] = p + __ldg(b2 + o);
    }
    float m = logit[0];
    #pragma unroll
    for (int o = 1; o < NOUT; ++o) m = fmaxf(m, logit[o]);
    float s = 0.0f;
    #pragma unroll
    for (int o = 0; o < NOUT; ++o) s += expf(logit[o] - m);
    const float lse = m + logf(s);
    if (lane < NOUT) out[(size_t)gw * NOUT + lane] = logit[lane] - lse;
}

// ---------------- launcher ----------------
extern "C" void kernel_launch(void* const* d_in, const int* in_sizes, int n_in,
                              void* d_out, int out_size) {
    const float* x        = (const float*)d_in[0];
    const float* L        = (const float*)d_in[1];
    const float* lmax     = (const float*)d_in[2];
    const float* cl1W     = (const float*)d_in[3];
    const float* cl1b     = (const float*)d_in[4];
    const float* fc1W     = (const float*)d_in[5];
    const float* fc1b     = (const float*)d_in[6];
    const float* bn_gamma = (const float*)d_in[7];
    const float* bn_beta  = (const float*)d_in[8];
    const float* bn_mean  = (const float*)d_in[9];
    const float* bn_var   = (const float*)d_in[10];
    const float* lin1W    = (const float*)d_in[11];
    const float* lin1b    = (const float*)d_in[12];
    const float* lin2W    = (const float*)d_in[13];
    const float* lin2b    = (const float*)d_in[14];
    float* out = (float*)d_out;

    float *pPool, *pZ1, *pZ2;
    cudaGetSymbolAddress((void**)&pPool, g_pool);
    cudaGetSymbolAddress((void**)&pZ1,  g_z1);
    cudaGetSymbolAddress((void**)&pZ2,  g_z2);

    // 1) sparse extraction of Lr + degree sort
    build_ell<<<(NV * 32 + 255) / 256, 256>>>(L, lmax);
    sort_nodes<<<1, 1024>>>();

    // 2) fused chebyshev + cl1 + relu + maxpool (512 thr, 2 nodes/thr, 2 CTAs/SM)
    const int smem = (CHEBK * NV * BT + 32) * (int)sizeof(float);  // 80128 B
    cudaFuncSetAttribute(cheby_fused, cudaFuncAttributeMaxDynamicSharedMemorySize, smem);
    cheby_fused<<<BATCH / BT, 512, smem>>>(x, cl1W, cl1b);

    // 3) fc1 + BN x4 + relu + JK-max  (M=8192, N=256, K=625)
    dim3 grid(HIDD / BN, BATCH / BM);   // (4, 64) = 256 CTAs
    gemm_nt<0><<<grid, 256>>>(pPool, fc1W, fc1b, bn_gamma, bn_beta, bn_mean, bn_var,
                              pZ1, POOLD, HIDD);

    // 4) lin1 + relu  (M=8192, N=256, K=256)
    gemm_nt<1><<<grid, 256>>>(pZ1, lin1W, lin1b, nullptr, nullptr, nullptr, nullptr,
                              pZ2, HIDD, HIDD);

    // 5) lin2 + log_softmax
    lin2_lsm<<<BATCH / 8, 256>>>(pZ2, lin2W, lin2b, out);
}

// round 7
// speedup vs baseline: 1.7578x; 1.6278x over previous
#include <cuda_runtime.h>
#include <cstdint>

#define BATCH 8192
#define NV    1000
#define CHEBK 5
#define NF    5
#define HIDD  256
#define NOUT  10
#define POOLD 625
#define MAXW  32
#define BT    8
#define NSLOT 1024

// ---------------- scratch ----------------
__device__ int2  g_ell[NV * MAXW];        // row-major ELL {col, val-bits}
__device__ int   g_ell_len[NV];
__device__ int   g_perm[NV];              // degree-sorted node order
__device__ int2  g_ellT[(NSLOT / 32) * MAXW * 32];  // lane-major: [grp][j][lane]
__device__ float g_pool[(size_t)BATCH * POOLD];
__device__ float g_z1[(size_t)BATCH * HIDD];
__device__ float g_z2[(size_t)BATCH * HIDD];

// ---------------- kernel 1: build ELL of Lr = 2*L/lmax - I (warp/row) ----------------
__global__ void build_ell(const float* __restrict__ L, const float* __restrict__ lmax) {
    const int warp = (blockIdx.x * blockDim.x + threadIdx.x) >> 5;
    const int lane = threadIdx.x & 31;
    if (warp >= NV) return;
    const int v = warp;
    const float inv = 2.0f / lmax[0];
    int cnt = 0;
    #pragma unroll 4
    for (int c = 0; c < (NV + 31) / 32; ++c) {
        const int u = c * 32 + lane;
        float val = 0.0f;
        if (u < NV) val = L[(size_t)v * NV + u] * inv - (u == v ? 1.0f : 0.0f);
        const bool nz = (val != 0.0f);
        const unsigned m = __ballot_sync(0xffffffffu, nz);
        if (nz) {
            const int idx = cnt + __popc(m & ((1u << lane) - 1u));
            if (idx < MAXW) g_ell[v * MAXW + idx] = make_int2(u, __float_as_int(val));
        }
        cnt += __popc(m);
    }
    if (lane == 0) g_ell_len[v] = cnt < MAXW ? cnt : MAXW;
}

// ---------------- kernel 1b: counting sort of nodes by degree -> g_perm ----------------
// Bin-internal order is nondeterministic (atomics) but results are invariant:
// perm only picks which thread computes which node; per-node fp-op order is fixed.
__global__ void sort_nodes() {
    __shared__ int hist[MAXW + 1];
    __shared__ int off[MAXW + 1];
    const int tid = threadIdx.x;
    if (tid <= MAXW) hist[tid] = 0;
    __syncthreads();
    for (int v = tid; v < NV; v += blockDim.x) atomicAdd(&hist[g_ell_len[v]], 1);
    __syncthreads();
    if (tid == 0) {
        int run = 0;
        for (int b = 0; b <= MAXW; ++b) { off[b] = run; run += hist[b]; }
    }
    __syncthreads();
    for (int v = tid; v < NV; v += blockDim.x) {
        const int pos = atomicAdd(&off[g_ell_len[v]], 1);
        g_perm[pos] = v;
    }
}

// ---------------- kernel 1c: lane-major transpose of sorted ELL ----------------
// Slot s (sorted order) -> group s>>5, lane s&31. Zero-pad to MAXW so the hop
// loop needs no per-lane bounds ({w=0, col=0} is a harmless FMA against T[0]).
__global__ void transpose_ell() {
    const int s = blockIdx.x * blockDim.x + threadIdx.x;
    if (s >= NSLOT) return;
    const int grp = s >> 5, lane = s & 31;
    int v = -1, len = 0;
    if (s < NV) { v = g_perm[s]; len = g_ell_len[v]; }
    int2* dst = g_ellT + grp * (MAXW * 32) + lane;
    for (int j = 0; j < MAXW; ++j)
        dst[j * 32] = (j < len) ? g_ell[v * MAXW + j] : make_int2(0, 0);
}

// ---------------- kernel 2: fused cheby + cl1 + relu + maxpool ----------------
// 1024 threads, one degree-sorted slot per thread, BT=8 batch columns.
// ELL reads are lane-major -> one coalesced 256B LDG.64 per warp per nnz (nL=2).
__global__ __launch_bounds__(1024, 1)
void cheby_fused(const float* __restrict__ x,
                 const float* __restrict__ W,
                 const float* __restrict__ bias) {
    extern __shared__ float sT[];                 // [CHEBK][NV][BT] + 32 floats
    float* sW = sT + CHEBK * NV * BT;
    const int b0  = blockIdx.x * BT;
    const int tid = threadIdx.x;

    if (tid < NF * CHEBK) sW[tid] = W[tid];
    if (tid < NF) sW[NF * CHEBK + tid] = bias[tid];

    // T0[v][bb] = x[b0+bb][v]  (coalesced in v)
    #pragma unroll
    for (int i = tid; i < NV * BT; i += 1024) {
        const int bb = i / NV, v = i - bb * NV;
        sT[v * BT + bb] = x[(size_t)(b0 + bb) * NV + v];
    }
    __syncthreads();

    const int slot = tid;
    const int grp  = tid >> 5, lane = tid & 31;
    int v = 0, len = 0;
    if (slot < NV) { v = g_perm[slot]; len = g_ell_len[v]; }
    const int lm = __reduce_max_sync(0xffffffffu, len);   // warp-uniform bound
    const int2* __restrict__ ep = g_ellT + grp * (MAXW * 32) + lane;

    #pragma unroll
    for (int k = 1; k < CHEBK; ++k) {
        const float* __restrict__ Tm1 = sT + (k - 1) * (NV * BT);
        float*       __restrict__ Tk  = sT + k * (NV * BT);
        float4 A0 = make_float4(0.f, 0.f, 0.f, 0.f);
        float4 A1 = make_float4(0.f, 0.f, 0.f, 0.f);
        #pragma unroll 2
        for (int j = 0; j < lm; ++j) {
            const int2 e = __ldg(&ep[j * 32]);        // coalesced across warp
            const float w = __int_as_float(e.y);
            const float4* tr = reinterpret_cast<const float4*>(Tm1 + e.x * BT);
            const float4 t0 = tr[0], t1 = tr[1];
            A0.x = fmaf(w, t0.x, A0.x); A0.y = fmaf(w, t0.y, A0.y);
            A0.z = fmaf(w, t0.z, A0.z); A0.w = fmaf(w, t0.w, A0.w);
            A1.x = fmaf(w, t1.x, A1.x); A1.y = fmaf(w, t1.y, A1.y);
            A1.z = fmaf(w, t1.z, A1.z); A1.w = fmaf(w, t1.w, A1.w);
        }
        if (slot < NV) {
            float4* to = reinterpret_cast<float4*>(Tk + v * BT);
            if (k == 1) {
                to[0] = A0; to[1] = A1;
            } else {
                const float4* m2 = reinterpret_cast<const float4*>(sT + (k - 2) * (NV * BT) + v * BT);
                const float4 ma = m2[0], mb = m2[1];
                to[0] = make_float4(2.f * A0.x - ma.x, 2.f * A0.y - ma.y,
                                    2.f * A0.z - ma.z, 2.f * A0.w - ma.w);
                to[1] = make_float4(2.f * A1.x - mb.x, 2.f * A1.y - mb.y,
                                    2.f * A1.z - mb.z, 2.f * A1.w - mb.w);
            }
        }
        __syncthreads();
    }

    // epilogue: 125 groups * 8 bb = 1000 items
    if (tid < 125 * BT) {
        const int bb = tid & (BT - 1);
        const int g  = tid / BT;
        float m[NF];
        #pragma unroll
        for (int f = 0; f < NF; ++f) m[f] = -3.4e38f;
        #pragma unroll
        for (int vi = 0; vi < 8; ++vi) {
            const int vv = g * 8 + vi;
            float t[CHEBK];
            #pragma unroll
            for (int k = 0; k < CHEBK; ++k) t[k] = sT[k * (NV * BT) + vv * BT + bb];
            #pragma unroll
            for (int f = 0; f < NF; ++f) {
                float s = sW[NF * CHEBK + f];
                #pragma unroll
                for (int k = 0; k < CHEBK; ++k) s = fmaf(sW[f * CHEBK + k], t[k], s);
                m[f] = fmaxf(m[f], s);
            }
        }
        float* op = g_pool + (size_t)(b0 + bb) * POOLD + g * NF;
        #pragma unroll
        for (int f = 0; f < NF; ++f) op[f] = fmaxf(m[f], 0.0f);
    }
}

// ---------------- kernels 3/4: SGEMM C = A @ Bw^T + fused epilogue (unchanged) ---------
#define BM 128
#define BN 64
#define BKg 16

template <int EPI>
__global__ __launch_bounds__(256, 3)
void gemm_nt(const float* __restrict__ A, const float* __restrict__ Bw,
             const float* __restrict__ bias,
             const float* __restrict__ bn_gamma, const float* __restrict__ bn_beta,
             const float* __restrict__ bn_mean,  const float* __restrict__ bn_var,
             float* __restrict__ C, int Kd, int N) {
    __shared__ float As[2][BKg][BM + 4];
    __shared__ float Bs[2][BKg][BN + 4];

    const int tid  = threadIdx.x;
    const int tx   = tid & 15;
    const int ty   = tid >> 4;
    const int row0 = blockIdx.y * BM;
    const int col0 = blockIdx.x * BN;

    float acc[8][4];
    #pragma unroll
    for (int i = 0; i < 8; ++i)
        #pragma unroll
        for (int j = 0; j < 4; ++j) acc[i][j] = 0.0f;

    const int ntiles = (Kd + BKg - 1) / BKg;

    float ra[8], rb[4];
    auto load_tile = [&](int kt) {
        #pragma unroll
        for (int i = 0; i < 8; ++i) {
            const int idx = tid + i * 256;
            const int mm = idx >> 4, kk = idx & 15;
            const int kg = kt + kk;
            ra[i] = (kg < Kd) ? A[(size_t)(row0 + mm) * Kd + kg] : 0.0f;
        }
        #pragma unroll
        for (int i = 0; i < 4; ++i) {
            const int idx = tid + i * 256;
            const int mm = idx >> 4, kk = idx & 15;
            const int kg = kt + kk;
            rb[i] = (kg < Kd) ? Bw[(size_t)(col0 + mm) * Kd + kg] : 0.0f;
        }
    };
    auto store_tile = [&](int p) {
        #pragma unroll
        for (int i = 0; i < 8; ++i) {
            const int idx = tid + i * 256;
            As[p][idx & 15][idx >> 4] = ra[i];
        }
        #pragma unroll
        for (int i = 0; i < 4; ++i) {
            const int idx = tid + i * 256;
            Bs[p][idx & 15][idx >> 4] = rb[i];
        }
    };

    load_tile(0);
    store_tile(0);
    __syncthreads();

    int p = 0;
    for (int t = 0; t < ntiles; ++t) {
        if (t + 1 < ntiles) load_tile((t + 1) * BKg);
        #pragma unroll
        for (int kk = 0; kk < BKg; ++kk) {
            const float4* ap = reinterpret_cast<const float4*>(&As[p][kk][ty * 8]);
            const float4  a0 = ap[0], a1 = ap[1];
            const float4  b0 = *reinterpret_cast<const float4*>(&Bs[p][kk][tx * 4]);
            const float a[8] = {a0.x, a0.y, a0.z, a0.w, a1.x, a1.y, a1.z, a1.w};
            const float b[4] = {b0.x, b0.y, b0.z, b0.w};
            #pragma unroll
            for (int i = 0; i < 8; ++i)
                #pragma unroll
                for (int j = 0; j < 4; ++j) acc[i][j] = fmaf(a[i], b[j], acc[i][j]);
        }
        if (t + 1 < ntiles) {
            __syncthreads();
            store_tile(p ^ 1);
            __syncthreads();
        }
        p ^= 1;
    }

    float cb[4], cs[4][4], ct[4][4];
    #pragma unroll
    for (int j = 0; j < 4; ++j) {
        const int col = col0 + tx * 4 + j;
        cb[j] = __ldg(bias + col);
        if (EPI == 0) {
            #pragma unroll
            for (int l = 0; l < 4; ++l) {
                const int idx = l * HIDD + col;
                const float s = __ldg(bn_gamma + idx) * rsqrtf(__ldg(bn_var + idx) + 1e-5f);
                cs[j][l] = s;
                ct[j][l] = __ldg(bn_beta + idx) - __ldg(bn_mean + idx) * s;
            }
        }
    }

    #pragma unroll
    for (int i = 0; i < 8; ++i) {
        const int row = row0 + ty * 8 + i;
        float4 o;
        float* ov = &o.x;
        #pragma unroll
        for (int j = 0; j < 4; ++j) {
            float y = acc[i][j] + cb[j];
            if (EPI == 0) {
                float z = 0.0f;
                #pragma unroll
                for (int l = 0; l < 4; ++l) {
                    y = fmaxf(fmaf(y, cs[j][l], ct[j][l]), 0.0f);
                    z = fmaxf(z, y);
                }
                ov[j] = z;
            } else {
                ov[j] = fmaxf(y, 0.0f);
            }
        }
        *reinterpret_cast<float4*>(&C[(size_t)row * N + col0 + tx * 4]) = o;
    }
}

// ---------------- kernel 5: lin2 + log_softmax ----------------
__global__ void lin2_lsm(const float* __restrict__ Z2, const float* __restrict__ W2,
                         const float* __restrict__ b2, float* __restrict__ out) {
    const int gw   = (blockIdx.x * blockDim.x + threadIdx.x) >> 5;
    const int lane = threadIdx.x & 31;
    if (gw >= BATCH) return;
    const float* zr = Z2 + (size_t)gw * HIDD;
    float z[8];
    #pragma unroll
    for (int j = 0; j < 8; ++j) z[j] = zr[lane + 32 * j];

    float logit[NOUT];
    #pragma unroll
    for (int o = 0; o < NOUT; ++o) {
        float p = 0.0f;
        #pragma unroll
        for (int j = 0; j < 8; ++j) p += z[j] * __ldg(W2 + o * HIDD + lane + 32 * j);
        #pragma unroll
        for (int off = 16; off; off >>= 1) p += __shfl_xor_sync(0xffffffffu, p, off);
        logit[o] = p + __ldg(b2 + o);
    }
    float m = logit[0];
    #pragma unroll
    for (int o = 1; o < NOUT; ++o) m = fmaxf(m, logit[o]);
    float s = 0.0f;
    #pragma unroll
    for (int o = 0; o < NOUT; ++o) s += expf(logit[o] - m);
    const float lse = m + logf(s);
    if (lane < NOUT) out[(size_t)gw * NOUT + lane] = logit[lane] - lse;
}

// ---------------- launcher ----------------
extern "C" void kernel_launch(void* const* d_in, const int* in_sizes, int n_in,
                              void* d_out, int out_size) {
    const float* x        = (const float*)d_in[0];
    const float* L        = (const float*)d_in[1];
    const float* lmax     = (const float*)d_in[2];
    const float* cl1W     = (const float*)d_in[3];
    const float* cl1b     = (const float*)d_in[4];
    const float* fc1W     = (const float*)d_in[5];
    const float* fc1b     = (const float*)d_in[6];
    const float* bn_gamma = (const float*)d_in[7];
    const float* bn_beta  = (const float*)d_in[8];
    const float* bn_mean  = (const float*)d_in[9];
    const float* bn_var   = (const float*)d_in[10];
    const float* lin1W    = (const float*)d_in[11];
    const float* lin1b    = (const float*)d_in[12];
    const float* lin2W    = (const float*)d_in[13];
    const float* lin2b    = (const float*)d_in[14];
    float* out = (float*)d_out;

    float *pPool, *pZ1, *pZ2;
    cudaGetSymbolAddress((void**)&pPool, g_pool);
    cudaGetSymbolAddress((void**)&pZ1,  g_z1);
    cudaGetSymbolAddress((void**)&pZ2,  g_z2);

    // 1) sparse extraction of Lr + degree sort + lane-major transpose
    build_ell<<<(NV * 32 + 255) / 256, 256>>>(L, lmax);
    sort_nodes<<<1, 1024>>>();
    transpose_ell<<<NSLOT / 256, 256>>>();

    // 2) fused chebyshev + cl1 + relu + maxpool
    const int smem = (CHEBK * NV * BT + 32) * (int)sizeof(float);  // 160128 B
    cudaFuncSetAttribute(cheby_fused, cudaFuncAttributeMaxDynamicSharedMemorySize, smem);
    cheby_fused<<<BATCH / BT, 1024, smem>>>(x, cl1W, cl1b);

    // 3) fc1 + BN x4 + relu + JK-max  (M=8192, N=256, K=625)
    dim3 grid(HIDD / BN, BATCH / BM);   // (4, 64) = 256 CTAs
    gemm_nt<0><<<grid, 256>>>(pPool, fc1W, fc1b, bn_gamma, bn_beta, bn_mean, bn_var,
                              pZ1, POOLD, HIDD);

    // 4) lin1 + relu  (M=8192, N=256, K=256)
    gemm_nt<1><<<grid, 256>>>(pZ1, lin1W, lin1b, nullptr, nullptr, nullptr, nullptr,
                              pZ2, HIDD, HIDD);

    // 5) lin2 + log_softmax
    lin2_lsm<<<BATCH / 8, 256>>>(pZ2, lin2W, lin2b, out);
}

// round 8
// speedup vs baseline: 1.9204x; 1.0925x over previous
#include <cuda_runtime.h>
#include <cstdint>

#define BATCH 8192
#define NV    1000
#define CHEBK 5
#define NF    5
#define HIDD  256
#define NOUT  10
#define POOLD 625
#define MAXW  32
#define BT    8
#define HBT   4
#define NSLOT 1024
#define PLANE (NV * HBT)            // floats per half-plane (4000)

// ---------------- scratch ----------------
__device__ int2  g_ell[NV * MAXW];
__device__ int   g_ell_len[NV];
__device__ int   g_perm[NV];
__device__ int2  g_ellT[(NSLOT / 32) * MAXW * 32];  // lane-major [grp][j][lane]
__device__ float g_pool[(size_t)BATCH * POOLD];
__device__ float g_z1[(size_t)BATCH * HIDD];
__device__ float g_z2[(size_t)BATCH * HIDD];

// ---------------- kernel 1: build ELL of Lr = 2*L/lmax - I (warp/row) ----------------
__global__ void build_ell(const float* __restrict__ L, const float* __restrict__ lmax) {
    const int warp = (blockIdx.x * blockDim.x + threadIdx.x) >> 5;
    const int lane = threadIdx.x & 31;
    if (warp >= NV) return;
    const int v = warp;
    const float inv = 2.0f / lmax[0];
    int cnt = 0;
    #pragma unroll 4
    for (int c = 0; c < (NV + 31) / 32; ++c) {
        const int u = c * 32 + lane;
        float val = 0.0f;
        if (u < NV) val = L[(size_t)v * NV + u] * inv - (u == v ? 1.0f : 0.0f);
        const bool nz = (val != 0.0f);
        const unsigned m = __ballot_sync(0xffffffffu, nz);
        if (nz) {
            const int idx = cnt + __popc(m & ((1u << lane) - 1u));
            if (idx < MAXW) g_ell[v * MAXW + idx] = make_int2(u, __float_as_int(val));
        }
        cnt += __popc(m);
    }
    if (lane == 0) g_ell_len[v] = cnt < MAXW ? cnt : MAXW;
}

// ---------------- kernel 1b: counting sort by degree -> g_perm ----------------
__global__ void sort_nodes() {
    __shared__ int hist[MAXW + 1];
    __shared__ int off[MAXW + 1];
    const int tid = threadIdx.x;
    if (tid <= MAXW) hist[tid] = 0;
    __syncthreads();
    for (int v = tid; v < NV; v += blockDim.x) atomicAdd(&hist[g_ell_len[v]], 1);
    __syncthreads();
    if (tid == 0) {
        int run = 0;
        for (int b = 0; b <= MAXW; ++b) { off[b] = run; run += hist[b]; }
    }
    __syncthreads();
    for (int v = tid; v < NV; v += blockDim.x) {
        const int pos = atomicAdd(&off[g_ell_len[v]], 1);
        g_perm[pos] = v;
    }
}

// ---------------- kernel 1c: lane-major transpose of sorted ELL ----------------
__global__ void transpose_ell() {
    const int s = blockIdx.x * blockDim.x + threadIdx.x;
    if (s >= NSLOT) return;
    const int grp = s >> 5, lane = s & 31;
    int v = -1, len = 0;
    if (s < NV) { v = g_perm[s]; len = g_ell_len[v]; }
    int2* dst = g_ellT + grp * (MAXW * 32) + lane;
    for (int j = 0; j < MAXW; ++j)
        dst[j * 32] = (j < len) ? g_ell[v * MAXW + j] : make_int2(0, 0);
}

// ---------------- kernel 2: fused cheby + cl1 + relu + maxpool ----------------
// Split-half batch layout: Lo[k][v][0..3], Hi[k][v][0..3]. Node stride = 16B so
// gather start-banks hit all 8 legal LDS.128 positions (conflict ~7 vs ~11).
__global__ __launch_bounds__(1024, 1)
void cheby_fused(const float* __restrict__ x,
                 const float* __restrict__ W,
                 const float* __restrict__ bias) {
    extern __shared__ float sT[];            // Lo[5][4000], Hi[5][4000], W/b[32]
    float* sLo = sT;
    float* sHi = sT + CHEBK * PLANE;
    float* sW  = sT + 2 * CHEBK * PLANE;
    const int b0  = blockIdx.x * BT;
    const int tid = threadIdx.x;

    if (tid < NF * CHEBK) sW[tid] = W[tid];
    if (tid < NF) sW[NF * CHEBK + tid] = bias[tid];

    // T0: lo half bb=0..3, hi half bb=4..7  (coalesced in v)
    #pragma unroll
    for (int i = tid; i < NV * BT; i += 1024) {
        const int bb = i / NV, v = i - bb * NV;
        const float val = x[(size_t)(b0 + bb) * NV + v];
        if (bb < HBT) sLo[v * HBT + bb] = val;
        else          sHi[v * HBT + (bb - HBT)] = val;
    }
    __syncthreads();

    const int slot = tid;
    const int grp  = tid >> 5, lane = tid & 31;
    int v = 0, len = 0;
    if (slot < NV) { v = g_perm[slot]; len = g_ell_len[v]; }
    const int lm = __reduce_max_sync(0xffffffffu, len);
    const int2* __restrict__ ep = g_ellT + grp * (MAXW * 32) + lane;

    #pragma unroll
    for (int k = 1; k < CHEBK; ++k) {
        const float* __restrict__ Lo1 = sLo + (k - 1) * PLANE;
        const float* __restrict__ Hi1 = sHi + (k - 1) * PLANE;
        float4 A0 = make_float4(0.f, 0.f, 0.f, 0.f);
        float4 A1 = make_float4(0.f, 0.f, 0.f, 0.f);
        #pragma unroll 2
        for (int j = 0; j < lm; ++j) {
            const int2 e = __ldg(&ep[j * 32]);       // coalesced 256B/warp
            const float w = __int_as_float(e.y);
            const float4 t0 = *reinterpret_cast<const float4*>(Lo1 + e.x * HBT);
            const float4 t1 = *reinterpret_cast<const float4*>(Hi1 + e.x * HBT);
            A0.x = fmaf(w, t0.x, A0.x); A0.y = fmaf(w, t0.y, A0.y);
            A0.z = fmaf(w, t0.z, A0.z); A0.w = fmaf(w, t0.w, A0.w);
            A1.x = fmaf(w, t1.x, A1.x); A1.y = fmaf(w, t1.y, A1.y);
            A1.z = fmaf(w, t1.z, A1.z); A1.w = fmaf(w, t1.w, A1.w);
        }
        if (slot < NV) {
            float4* toL = reinterpret_cast<float4*>(sLo + k * PLANE + v * HBT);
            float4* toH = reinterpret_cast<float4*>(sHi + k * PLANE + v * HBT);
            if (k == 1) {
                *toL = A0; *toH = A1;
            } else {
                const float4 ma = *reinterpret_cast<const float4*>(sLo + (k - 2) * PLANE + v * HBT);
                const float4 mb = *reinterpret_cast<const float4*>(sHi + (k - 2) * PLANE + v * HBT);
                *toL = make_float4(2.f * A0.x - ma.x, 2.f * A0.y - ma.y,
                                   2.f * A0.z - ma.z, 2.f * A0.w - ma.w);
                *toH = make_float4(2.f * A1.x - mb.x, 2.f * A1.y - mb.y,
                                   2.f * A1.z - mb.z, 2.f * A1.w - mb.w);
            }
        }
        __syncthreads();
    }

    // epilogue: 125 groups * 8 bb = 1000 items
    if (tid < 125 * BT) {
        const int bb = tid & (BT - 1);
        const int g  = tid / BT;
        const float* base = (bb < HBT) ? sLo : sHi;
        const int bo = bb & (HBT - 1);
        float m[NF];
        #pragma unroll
        for (int f = 0; f < NF; ++f) m[f] = -3.4e38f;
        #pragma unroll
        for (int vi = 0; vi < 8; ++vi) {
            const int vv = g * 8 + vi;
            float t[CHEBK];
            #pragma unroll
            for (int k = 0; k < CHEBK; ++k) t[k] = base[k * PLANE + vv * HBT + bo];
            #pragma unroll
            for (int f = 0; f < NF; ++f) {
                float s = sW[NF * CHEBK + f];
                #pragma unroll
                for (int k = 0; k < CHEBK; ++k) s = fmaf(sW[f * CHEBK + k], t[k], s);
                m[f] = fmaxf(m[f], s);
            }
        }
        float* op = g_pool + (size_t)(b0 + bb) * POOLD + g * NF;
        #pragma unroll
        for (int f = 0; f < NF; ++f) op[f] = fmaxf(m[f], 0.0f);
    }
}

// ---------------- kernels 3/4: SGEMM C = A @ Bw^T + fused epilogue (unchanged) ---------
#define BM 128
#define BN 64
#define BKg 16

template <int EPI>
__global__ __launch_bounds__(256, 3)
void gemm_nt(const float* __restrict__ A, const float* __restrict__ Bw,
             const float* __restrict__ bias,
             const float* __restrict__ bn_gamma, const float* __restrict__ bn_beta,
             const float* __restrict__ bn_mean,  const float* __restrict__ bn_var,
             float* __restrict__ C, int Kd, int N) {
    __shared__ float As[2][BKg][BM + 4];
    __shared__ float Bs[2][BKg][BN + 4];

    const int tid  = threadIdx.x;
    const int tx   = tid & 15;
    const int ty   = tid >> 4;
    const int row0 = blockIdx.y * BM;
    const int col0 = blockIdx.x * BN;

    float acc[8][4];
    #pragma unroll
    for (int i = 0; i < 8; ++i)
        #pragma unroll
        for (int j = 0; j < 4; ++j) acc[i][j] = 0.0f;

    const int ntiles = (Kd + BKg - 1) / BKg;

    float ra[8], rb[4];
    auto load_tile = [&](int kt) {
        #pragma unroll
        for (int i = 0; i < 8; ++i) {
            const int idx = tid + i * 256;
            const int mm = idx >> 4, kk = idx & 15;
            const int kg = kt + kk;
            ra[i] = (kg < Kd) ? A[(size_t)(row0 + mm) * Kd + kg] : 0.0f;
        }
        #pragma unroll
        for (int i = 0; i < 4; ++i) {
            const int idx = tid + i * 256;
            const int mm = idx >> 4, kk = idx & 15;
            const int kg = kt + kk;
            rb[i] = (kg < Kd) ? Bw[(size_t)(col0 + mm) * Kd + kg] : 0.0f;
        }
    };
    auto store_tile = [&](int p) {
        #pragma unroll
        for (int i = 0; i < 8; ++i) {
            const int idx = tid + i * 256;
            As[p][idx & 15][idx >> 4] = ra[i];
        }
        #pragma unroll
        for (int i = 0; i < 4; ++i) {
            const int idx = tid + i * 256;
            Bs[p][idx & 15][idx >> 4] = rb[i];
        }
    };

    load_tile(0);
    store_tile(0);
    __syncthreads();

    int p = 0;
    for (int t = 0; t < ntiles; ++t) {
        if (t + 1 < ntiles) load_tile((t + 1) * BKg);
        #pragma unroll
        for (int kk = 0; kk < BKg; ++kk) {
            const float4* ap = reinterpret_cast<const float4*>(&As[p][kk][ty * 8]);
            const float4  a0 = ap[0], a1 = ap[1];
            const float4  b0 = *reinterpret_cast<const float4*>(&Bs[p][kk][tx * 4]);
            const float a[8] = {a0.x, a0.y, a0.z, a0.w, a1.x, a1.y, a1.z, a1.w};
            const float b[4] = {b0.x, b0.y, b0.z, b0.w};
            #pragma unroll
            for (int i = 0; i < 8; ++i)
                #pragma unroll
                for (int j = 0; j < 4; ++j) acc[i][j] = fmaf(a[i], b[j], acc[i][j]);
        }
        if (t + 1 < ntiles) {
            __syncthreads();
            store_tile(p ^ 1);
            __syncthreads();
        }
        p ^= 1;
    }

    float cb[4], cs[4][4], ct[4][4];
    #pragma unroll
    for (int j = 0; j < 4; ++j) {
        const int col = col0 + tx * 4 + j;
        cb[j] = __ldg(bias + col);
        if (EPI == 0) {
            #pragma unroll
            for (int l = 0; l < 4; ++l) {
                const int idx = l * HIDD + col;
                const float s = __ldg(bn_gamma + idx) * rsqrtf(__ldg(bn_var + idx) + 1e-5f);
                cs[j][l] = s;
                ct[j][l] = __ldg(bn_beta + idx) - __ldg(bn_mean + idx) * s;
            }
        }
    }

    #pragma unroll
    for (int i = 0; i < 8; ++i) {
        const int row = row0 + ty * 8 + i;
        float4 o;
        float* ov = &o.x;
        #pragma unroll
        for (int j = 0; j < 4; ++j) {
            float y = acc[i][j] + cb[j];
            if (EPI == 0) {
                float z = 0.0f;
                #pragma unroll
                for (int l = 0; l < 4; ++l) {
                    y = fmaxf(fmaf(y, cs[j][l], ct[j][l]), 0.0f);
                    z = fmaxf(z, y);
                }
                ov[j] = z;
            } else {
                ov[j] = fmaxf(y, 0.0f);
            }
        }
        *reinterpret_cast<float4*>(&C[(size_t)row * N + col0 + tx * 4]) = o;
    }
}

// ---------------- kernel 5: lin2 + log_softmax ----------------
__global__ void lin2_lsm(const float* __restrict__ Z2, const float* __restrict__ W2,
                         const float* __restrict__ b2, float* __restrict__ out) {
    const int gw   = (blockIdx.x * blockDim.x + threadIdx.x) >> 5;
    const int lane = threadIdx.x & 31;
    if (gw >= BATCH) return;
    const float* zr = Z2 + (size_t)gw * HIDD;
    float z[8];
    #pragma unroll
    for (int j = 0; j < 8; ++j) z[j] = zr[lane + 32 * j];

    float logit[NOUT];
    #pragma unroll
    for (int o = 0; o < NOUT; ++o) {
        float p = 0.0f;
        #pragma unroll
        for (int j = 0; j < 8; ++j) p += z[j] * __ldg(W2 + o * HIDD + lane + 32 * j);
        #pragma unroll
        for (int off = 16; off; off >>= 1) p += __shfl_xor_sync(0xffffffffu, p, off);
        logit[o] = p + __ldg(b2 + o);
    }
    float m = logit[0];
    #pragma unroll
    for (int o = 1; o < NOUT; ++o) m = fmaxf(m, logit[o]);
    float s = 0.0f;
    #pragma unroll
    for (int o = 0; o < NOUT; ++o) s += expf(logit[o] - m);
    const float lse = m + logf(s);
    if (lane < NOUT) out[(size_t)gw * NOUT + lane] = logit[lane] - lse;
}

// ---------------- launcher ----------------
extern "C" void kernel_launch(void* const* d_in, const int* in_sizes, int n_in,
                              void* d_out, int out_size) {
    const float* x        = (const float*)d_in[0];
    const float* L        = (const float*)d_in[1];
    const float* lmax     = (const float*)d_in[2];
    const float* cl1W     = (const float*)d_in[3];
    const float* cl1b     = (const float*)d_in[4];
    const float* fc1W     = (const float*)d_in[5];
    const float* fc1b     = (const float*)d_in[6];
    const float* bn_gamma = (const float*)d_in[7];
    const float* bn_beta  = (const float*)d_in[8];
    const float* bn_mean  = (const float*)d_in[9];
    const float* bn_var   = (const float*)d_in[10];
    const float* lin1W    = (const float*)d_in[11];
    const float* lin1b    = (const float*)d_in[12];
    const float* lin2W    = (const float*)d_in[13];
    const float* lin2b    = (const float*)d_in[14];
    float* out = (float*)d_out;

    float *pPool, *pZ1, *pZ2;
    cudaGetSymbolAddress((void**)&pPool, g_pool);
    cudaGetSymbolAddress((void**)&pZ1,  g_z1);
    cudaGetSymbolAddress((void**)&pZ2,  g_z2);

    // 1) sparse extraction of Lr + degree sort + lane-major transpose
    build_ell<<<(NV * 32 + 255) / 256, 256>>>(L, lmax);
    sort_nodes<<<1, 1024>>>();
    transpose_ell<<<NSLOT / 256, 256>>>();

    // 2) fused chebyshev + cl1 + relu + maxpool (split-half planes)
    const int smem = (2 * CHEBK * PLANE + 32) * (int)sizeof(float);  // 160128 B
    cudaFuncSetAttribute(cheby_fused, cudaFuncAttributeMaxDynamicSharedMemorySize, smem);
    cheby_fused<<<BATCH / BT, 1024, smem>>>(x, cl1W, cl1b);

    // 3) fc1 + BN x4 + relu + JK-max  (M=8192, N=256, K=625)
    dim3 grid(HIDD / BN, BATCH / BM);   // (4, 64) = 256 CTAs
    gemm_nt<0><<<grid, 256>>>(pPool, fc1W, fc1b, bn_gamma, bn_beta, bn_mean, bn_var,
                              pZ1, POOLD, HIDD);

    // 4) lin1 + relu  (M=8192, N=256, K=256)
    gemm_nt<1><<<grid, 256>>>(pZ1, lin1W, lin1b, nullptr, nullptr, nullptr, nullptr,
                              pZ2, HIDD, HIDD);

    // 5) lin2 + log_softmax
    lin2_lsm<<<BATCH / 8, 256>>>(pZ2, lin2W, lin2b, out);
}